// round 5
// baseline (speedup 1.0000x reference)
#include <cuda_runtime.h>
#include <cuda_bf16.h>
#include <cfloat>
#include <cstdint>

#define NUM_HEADS 4
#define OUT_DIM   256
#define HID       512
#define NQ        256
#define TOPK      16
#define N_MEM_MAX 500000
#define CAND      64
#define CPB       6
#define NBLK_MAX  160
#define POOL_MAX  (NBLK_MAX * CPB)   // 960

// ---------------- static scratch ---------------------------------------------
__device__ __align__(16) float    g_qpre[64 * NUM_HEADS * OUT_DIM];
__device__ __align__(16) float    g_q  [NQ * OUT_DIM];
__device__ __align__(16) uint16_t g_qf8[NQ * (OUT_DIM / 2)];   // e4m3 pairs
__device__ float g_cand_val[NQ * POOL_MAX];
__device__ int   g_cand_idx[NQ * POOL_MAX];

// ---------------- helpers ------------------------------------------------------
__device__ __forceinline__ uint32_t smem_u32(const void* p) {
    return (uint32_t)__cvta_generic_to_shared(p);
}
__device__ __forceinline__ uint16_t cvt_e4m3x2(float hi, float lo) {
    uint16_t r;
    asm("cvt.rn.satfinite.e4m3x2.f32 %0, %1, %2;" : "=h"(r) : "f"(hi), "f"(lo));
    return r;
}
__device__ __forceinline__ void ldsm_x4(uint32_t& r0, uint32_t& r1, uint32_t& r2, uint32_t& r3,
                                        uint32_t addr) {
    asm volatile("ldmatrix.sync.aligned.m8n8.x4.shared.b16 {%0,%1,%2,%3}, [%4];"
                 : "=r"(r0), "=r"(r1), "=r"(r2), "=r"(r3) : "r"(addr));
}
__device__ __forceinline__ void mma_fp8(float* d,
                                        uint32_t a0, uint32_t a1, uint32_t a2, uint32_t a3,
                                        uint32_t b0, uint32_t b1) {
    asm volatile("mma.sync.aligned.m16n8k32.row.col.f32.e4m3.e4m3.f32 "
                 "{%0,%1,%2,%3}, {%4,%5,%6,%7}, {%8,%9}, {%0,%1,%2,%3};"
                 : "+f"(d[0]), "+f"(d[1]), "+f"(d[2]), "+f"(d[3])
                 : "r"(a0), "r"(a1), "r"(a2), "r"(a3), "r"(b0), "r"(b1));
}
__device__ __forceinline__ void cp_async16(uint32_t dst, const float* src, uint32_t sz) {
    asm volatile("cp.async.cg.shared.global [%0], [%1], 16, %2;"
                 :: "r"(dst), "l"(src), "r"(sz) : "memory");
}
#define CP_COMMIT() asm volatile("cp.async.commit_group;" ::: "memory")
#define CP_WAIT0()  asm volatile("cp.async.wait_group 0;" ::: "memory")

// ---------------- K1a: proj = hidden @ Wp + bp --------------------------------
__global__ __launch_bounds__(256) void proj_kernel(const float* __restrict__ hidden,
                                                   const float* __restrict__ Wp,
                                                   const float* __restrict__ bp) {
    const int tid = threadIdx.x;
    const int j   = blockIdx.x * 32 + (tid & 31);
    const int b0  = (tid >> 5) * 8;
    float acc[8];
#pragma unroll
    for (int i = 0; i < 8; i++) acc[i] = 0.f;
#pragma unroll 4
    for (int k = 0; k < HID; k++) {
        const float wv = __ldg(&Wp[k * (NUM_HEADS * OUT_DIM) + j]);
#pragma unroll
        for (int i = 0; i < 8; i++)
            acc[i] = fmaf(__ldg(&hidden[(b0 + i) * HID + k]), wv, acc[i]);
    }
    const float bias = __ldg(&bp[j]);
#pragma unroll
    for (int i = 0; i < 8; i++)
        g_qpre[(b0 + i) * (NUM_HEADS * OUT_DIM) + j] = acc[i] + bias;
}

// ---------------- K1b: layernorm ----------------------------------------------
__global__ __launch_bounds__(256) void ln_kernel() {
    __shared__ float red[OUT_DIM];
    __shared__ float ov[OUT_DIM];
    const int qidx = blockIdx.x;
    const int h = qidx >> 6, b = qidx & 63, d = threadIdx.x;

    const float x = g_qpre[b * (NUM_HEADS * OUT_DIM) + h * OUT_DIM + d];
    red[d] = x; __syncthreads();
    for (int s = 128; s > 0; s >>= 1) { if (d < s) red[d] += red[d + s]; __syncthreads(); }
    const float mean = red[0] * (1.0f / OUT_DIM);
    __syncthreads();
    const float dx = x - mean;
    red[d] = dx * dx; __syncthreads();
    for (int s = 128; s > 0; s >>= 1) { if (d < s) red[d] += red[d + s]; __syncthreads(); }
    const float var = red[0] * (1.0f / OUT_DIM);

    const float o = dx * rsqrtf(var + 1e-5f);
    g_q[qidx * OUT_DIM + d] = o;
    ov[d] = o;
    __syncthreads();
    if (d < 128)
        g_qf8[qidx * 128 + d] = cvt_e4m3x2(ov[2 * d + 1], ov[2 * d]);
}

// ---------------- K2: fp8 mma scores + fused per-block top-6 -------------------
// smem: B fp8 [256 q][272B] | A32 fp32 [64 r][4 seg][272B] | A8 [64 r][272B] | Sb bf16 [64][260]
#define B_OFF    0
#define B_STR    272
#define A32_OFF  69632
#define A32_RSTR 1088
#define A8_OFF   139264
#define A8_STR   272
#define SB_OFF   156672
#define SBP      260
#define K2_SMEM  190016

#define INS6(v, r)                                                        \
    do {                                                                  \
        t6v[tminpos] = (v); t6i[tminpos] = (r);                           \
        tmin = t6v[0]; tminpos = 0;                                       \
        _Pragma("unroll")                                                 \
        for (int jj = 1; jj < CPB; jj++)                                  \
            if (t6v[jj] < tmin) { tmin = t6v[jj]; tminpos = jj; }         \
    } while (0)

__global__ __launch_bounds__(256, 1) void score_kernel(const float* __restrict__ mem,
                                                       int n_mem, int ntiles) {
    extern __shared__ char sm[];
    const int tid = threadIdx.x, lane = tid & 31, w = tid >> 5;
    const int wm = w >> 2, wn = w & 3;           // 2 row-groups x 4 q-groups
    const uint32_t sb = smem_u32(sm);

    // B fill: 256 q rows x 256B e4m3, row stride 272B
    {
        const uint4* src = (const uint4*)g_qf8;   // 16B = 8 u16 = 16 fp8
#pragma unroll
        for (int i = 0; i < 16; i++) {
            const int p = tid + i * 256;
            const int q = p >> 4, ch = p & 15;
            *(uint4*)(sm + B_OFF + q * B_STR + ch * 16) = src[q * 16 + ch];
        }
    }

    float t6v[CPB]; int t6i[CPB];
#pragma unroll
    for (int j = 0; j < CPB; j++) { t6v[j] = -FLT_MAX; t6i[j] = 0x7FFFFFFF; }
    float tmin = -FLT_MAX; int tminpos = 0;

    const int cr = tid >> 2, cs = tid & 3;       // this thread's A block (row, seg)
    const uint32_t a32dst = sb + A32_OFF + cr * A32_RSTR + cs * B_STR;

    // issue first tile
    {
        const int rg = blockIdx.x * 64 + cr;
        const float* src = mem + (size_t)min(rg, n_mem - 1) * OUT_DIM + cs * 64;
        const uint32_t sz = (rg < n_mem) ? 16u : 0u;
#pragma unroll
        for (int i = 0; i < 16; i++) cp_async16(a32dst + i * 16, src + i * 4, sz);
        CP_COMMIT();
    }
    __syncthreads();   // B visible

    const uint32_t aB = sb + A8_OFF + (wm * 32 + (lane & 15)) * A8_STR + (lane >> 4) * 16;
    const uint32_t bB = sb + B_OFF + (wn * 64 + (lane & 15)) * B_STR + (lane >> 4) * 16;
    __nv_bfloat16* Sb = (__nv_bfloat16*)(sm + SB_OFF);

    for (int t = blockIdx.x; t < ntiles; t += gridDim.x) {
        CP_WAIT0();
        // convert own fp32 block -> e4m3 (conflict-free: 272-word row stride)
        {
            const char* s32 = sm + A32_OFF + cr * A32_RSTR + cs * B_STR;
            char* d8 = sm + A8_OFF + cr * A8_STR + cs * 64;
#pragma unroll
            for (int i = 0; i < 4; i++) {
                const float4 f0 = *(const float4*)(s32 + i * 64 + 0);
                const float4 f1 = *(const float4*)(s32 + i * 64 + 16);
                const float4 f2 = *(const float4*)(s32 + i * 64 + 32);
                const float4 f3 = *(const float4*)(s32 + i * 64 + 48);
                uint4 o;
                o.x = (uint32_t)cvt_e4m3x2(f0.y, f0.x) | ((uint32_t)cvt_e4m3x2(f0.w, f0.z) << 16);
                o.y = (uint32_t)cvt_e4m3x2(f1.y, f1.x) | ((uint32_t)cvt_e4m3x2(f1.w, f1.z) << 16);
                o.z = (uint32_t)cvt_e4m3x2(f2.y, f2.x) | ((uint32_t)cvt_e4m3x2(f2.w, f2.z) << 16);
                o.w = (uint32_t)cvt_e4m3x2(f3.y, f3.x) | ((uint32_t)cvt_e4m3x2(f3.w, f3.z) << 16);
                *(uint4*)(d8 + i * 16) = o;
            }
        }
        __syncthreads();   // A8 ready, A32 free

        // prefetch next tile (overlaps mma + selection)
        const int tn = t + gridDim.x;
        if (tn < ntiles) {
            const int rg = tn * 64 + cr;
            const float* src = mem + (size_t)min(rg, n_mem - 1) * OUT_DIM + cs * 64;
            const uint32_t sz = (rg < n_mem) ? 16u : 0u;
#pragma unroll
            for (int i = 0; i < 16; i++) cp_async16(a32dst + i * 16, src + i * 4, sz);
            CP_COMMIT();
        }

        // ---- fp8 mma: 64 rows x 256 q x k256 ----
        float acc[2][8][4];
#pragma unroll
        for (int mt = 0; mt < 2; mt++)
#pragma unroll
            for (int nt = 0; nt < 8; nt++)
#pragma unroll
                for (int c = 0; c < 4; c++) acc[mt][nt][c] = 0.f;

#pragma unroll
        for (int kt = 0; kt < 8; kt++) {
            uint32_t a0, a1, a2, a3, a4, a5, a6, a7;
            ldsm_x4(a0, a1, a2, a3, aB + kt * 32);
            ldsm_x4(a4, a5, a6, a7, aB + 16 * A8_STR + kt * 32);
#pragma unroll
            for (int qg = 0; qg < 4; qg++) {
                uint32_t b0, b1, b2, b3;
                ldsm_x4(b0, b1, b2, b3, bB + qg * 16 * B_STR + kt * 32);
                mma_fp8(acc[0][qg * 2 + 0], a0, a1, a2, a3, b0, b2);
                mma_fp8(acc[0][qg * 2 + 1], a0, a1, a2, a3, b1, b3);
                mma_fp8(acc[1][qg * 2 + 0], a4, a5, a6, a7, b0, b2);
                mma_fp8(acc[1][qg * 2 + 1], a4, a5, a6, a7, b1, b3);
            }
        }

        // scores -> Sb [64 r][256 q] bf16
#pragma unroll
        for (int mt = 0; mt < 2; mt++) {
            const int rl = wm * 32 + mt * 16 + (lane >> 2);
#pragma unroll
            for (int nt = 0; nt < 8; nt++) {
                const int q = wn * 64 + nt * 8 + (lane & 3) * 2;
                *(__nv_bfloat162*)(Sb + rl * SBP + q) =
                    __float22bfloat162_rn(make_float2(acc[mt][nt][0], acc[mt][nt][1]));
                *(__nv_bfloat162*)(Sb + (rl + 8) * SBP + q) =
                    __float22bfloat162_rn(make_float2(acc[mt][nt][2], acc[mt][nt][3]));
            }
        }
        __syncthreads();   // scores ready; all mma done (A8 safe to rewrite next iter)

        // fused selection: thread tid owns query tid
        const int rb = t * 64;
        const int rcap = n_mem - rb;
#pragma unroll 4
        for (int r = 0; r < 64; r++) {
            const float v = __bfloat162float(Sb[r * SBP + tid]);
            if (v > tmin && r < rcap) INS6(v, rb + r);
        }
        // no barrier needed: next-iter post-convert barrier orders Sb reuse
    }

    const int ob = (tid * gridDim.x + blockIdx.x) * CPB;
#pragma unroll
    for (int j = 0; j < CPB; j++) { g_cand_val[ob + j] = t6v[j]; g_cand_idx[ob + j] = t6i[j]; }
}

// ---------------- K3: merge -> coarse top-64 -> exact rescore -> top-16 -------
__global__ __launch_bounds__(256) void final_kernel(const float* __restrict__ mem,
                                                    float* __restrict__ out,
                                                    int n_mem, int nblk) {
    __shared__ float sv[POOL_MAX];
    __shared__ int   si[POOL_MAX];
    __shared__ float swv[8]; __shared__ int swi[8]; __shared__ int swp[8];
    __shared__ int   ci[CAND];
    __shared__ float ev[CAND];
    __shared__ float wv[TOPK]; __shared__ int wi[TOPK];

    const int q = blockIdx.x, tid = threadIdx.x, lane = tid & 31, w = tid >> 5;
    const int P = nblk * CPB;

    for (int j = tid; j < P; j += 256) {
        sv[j] = g_cand_val[q * P + j];
        si[j] = g_cand_idx[q * P + j];
    }
    __syncthreads();

    for (int kk = 0; kk < CAND; kk++) {
        float best = -FLT_MAX; int besti = 0x7FFFFFFF, bestp = 0;
        for (int j = tid; j < P; j += 256) {
            const float v = sv[j]; const int id = si[j];
            if (v > best || (v == best && id < besti)) { best = v; besti = id; bestp = j; }
        }
#pragma unroll
        for (int o = 16; o; o >>= 1) {
            const float ovv = __shfl_down_sync(0xffffffffu, best, o);
            const int   oi = __shfl_down_sync(0xffffffffu, besti, o);
            const int   op = __shfl_down_sync(0xffffffffu, bestp, o);
            if (ovv > best || (ovv == best && oi < besti)) { best = ovv; besti = oi; bestp = op; }
        }
        if (lane == 0) { swv[w] = best; swi[w] = besti; swp[w] = bestp; }
        __syncthreads();
        if (tid < 8) {
            best = swv[tid]; besti = swi[tid]; bestp = swp[tid];
#pragma unroll
            for (int o = 4; o; o >>= 1) {
                const float ovv = __shfl_down_sync(0xffu, best, o);
                const int   oi = __shfl_down_sync(0xffu, besti, o);
                const int   op = __shfl_down_sync(0xffu, bestp, o);
                if (ovv > best || (ovv == best && oi < besti)) { best = ovv; besti = oi; bestp = op; }
            }
            if (tid == 0) { ci[kk] = besti; sv[bestp] = -FLT_MAX; }
        }
        __syncthreads();
    }

    // exact fp32 rescore of 64 candidates
    const float* qv = g_q + q * OUT_DIM;
    for (int c = w; c < CAND; c += 8) {
        const int id = ci[c];
        float sum = 0.f;
        if (id < n_mem) {
            const float* row = mem + (size_t)id * OUT_DIM;
#pragma unroll
            for (int d = lane; d < OUT_DIM; d += 32) sum += row[d] * qv[d];
        }
#pragma unroll
        for (int o = 16; o; o >>= 1) sum += __shfl_xor_sync(0xffffffffu, sum, o);
        if (lane == 0) ev[c] = (id < n_mem) ? sum : -FLT_MAX;
    }
    __syncthreads();

    if (tid == 0) {
        unsigned long long used = 0ull;
        for (int kk = 0; kk < TOPK; kk++) {
            float best = -FLT_MAX; int besti = 0x7FFFFFFF; int bp = 0;
            for (int c = 0; c < CAND; c++) {
                if (used & (1ull << c)) continue;
                if (ev[c] > best || (ev[c] == best && ci[c] < besti)) {
                    best = ev[c]; besti = ci[c]; bp = c;
                }
            }
            used |= (1ull << bp); wv[kk] = best; wi[kk] = besti;
        }
    }
    __syncthreads();

    float* out_scores = out;
    float* out_idx    = out + NQ * TOPK;
    float* out_feats  = out + 2 * NQ * TOPK;

    if (tid < TOPK) {
        out_scores[q * TOPK + tid] = wv[tid];
        out_idx[q * TOPK + tid]    = (float)wi[tid];
    }
#pragma unroll 1
    for (int kk = 0; kk < TOPK; kk++)
        out_feats[(size_t)(q * TOPK + kk) * OUT_DIM + tid] = mem[(size_t)wi[kk] * OUT_DIM + tid];
}

// ---------------- launch ------------------------------------------------------
extern "C" void kernel_launch(void* const* d_in, const int* in_sizes, int n_in,
                              void* d_out, int out_size) {
    const float* hidden = (const float*)d_in[0];
    const float* Wp     = (const float*)d_in[1];
    const float* bp     = (const float*)d_in[2];
    const float* mem    = (const float*)d_in[3];
    int n_mem = in_sizes[3] / OUT_DIM;
    if (n_mem > N_MEM_MAX) n_mem = N_MEM_MAX;
    const int ntiles = (n_mem + 63) / 64;

    int dev = 0;
    cudaGetDevice(&dev);
    int nsm = 148;
    cudaDeviceGetAttribute(&nsm, cudaDevAttrMultiProcessorCount, dev);
    if (nsm < 1) nsm = 148;
    if (nsm > NBLK_MAX) nsm = NBLK_MAX;
    if (nsm > ntiles) nsm = ntiles;

    cudaFuncSetAttribute(score_kernel, cudaFuncAttributeMaxDynamicSharedMemorySize, K2_SMEM);

    proj_kernel<<<(NUM_HEADS * OUT_DIM) / 32, 256>>>(hidden, Wp, bp);
    ln_kernel<<<NQ, 256>>>();
    score_kernel<<<nsm, 256, K2_SMEM>>>(mem, n_mem, ntiles);
    final_kernel<<<NQ, 256>>>(mem, (float*)d_out, n_mem, nsm);
}